// round 4
// baseline (speedup 1.0000x reference)
#include <cuda_runtime.h>

// AtomicConv edge aggregation, round 3: stream compaction.
// K0: zero the worklist counter.
// K1: zero output + classify edges, warp-aggregated compaction into g_list.
// K2: grid-stride over compact list (full warps): weights + vector RED.

#define MAX_EDGES (1 << 20)
__device__ unsigned g_count;
__device__ uint2 g_list[MAX_EDGES];   // {edge_id, dst*8 + t}

__global__ void zero_counter_kernel() { g_count = 0u; }

__global__ __launch_bounds__(256) void prep_kernel(
    float4* __restrict__ out, int n4,
    const float* __restrict__ feat,   // (N)
    const float* __restrict__ ftu,    // (8)
    const int*   __restrict__ src,    // (E)
    const int*   __restrict__ dstv,   // (E)
    int n_edges)
{
    int i = blockIdx.x * 256 + threadIdx.x;
    if (i < n4) out[i] = make_float4(0.f, 0.f, 0.f, 0.f);

    bool active = false;
    int t = -1, d = 0;
    if (i < n_edges) {
        int s = __ldg(src + i);
        float f = __ldg(feat + s);
        #pragma unroll
        for (int j = 0; j < 8; j++)
            if (f == __ldg(ftu + j)) t = j;
        if (t >= 0) {
            active = true;
            d = __ldg(dstv + i);
        }
    }

    unsigned mask = __ballot_sync(0xffffffffu, active);
    if (mask) {
        int lane = threadIdx.x & 31;
        int leader = __ffs(mask) - 1;
        unsigned pos = 0;
        if (lane == leader) pos = atomicAdd(&g_count, (unsigned)__popc(mask));
        pos = __shfl_sync(0xffffffffu, pos, leader);
        pos += (unsigned)__popc(mask & ((1u << lane) - 1u));
        if (active) g_list[pos] = make_uint2((unsigned)i, (unsigned)((d << 3) | t));
    }
}

__device__ __forceinline__ float edge_weight(float d, float cut, float mean,
                                             float sc, float hpoc) {
    // 0.5*(cos(pi*d/cut)+1) == cos^2(pi*d/(2*cut))
    float c = __cosf(d * hpoc);
    float cv = c * c;
    cv = (d <= cut) ? cv : 0.f;
    float dm = d - mean;
    return cv * __expf(-sc * dm * dm);
}

__global__ __launch_bounds__(256) void compute_kernel(
    const float* __restrict__ dist,   // (E)  16 contiguous dists per edge at r*16
    const float* __restrict__ rp,     // (16,3) [cutoff, mean, scaling]
    float*       __restrict__ out,    // (N,128)
    int epb)
{
    unsigned total = g_count;
    unsigned stride = gridDim.x * 256;

    for (unsigned i = blockIdx.x * 256 + threadIdx.x; i < total; i += stride) {
        uint2 rec = g_list[i];
        int e = (int)rec.x;
        int q = e / epb;                 // radial kernel index
        int r = e - q * epb;

        float cut  = __ldg(rp + 3 * q + 0);
        float mean = __ldg(rp + 3 * q + 1);
        float sc   = __ldg(rp + 3 * q + 2);
        float hpoc = 1.57079632679489662f / cut;   // pi/(2*cut)

        const float4* dp = reinterpret_cast<const float4*>(dist) + (r << 2);
        float4* op = reinterpret_cast<float4*>(out)
                   + (((int)(rec.y >> 3)) << 5) + (((int)(rec.y & 7u)) << 2);

        float4 d4[4];
        #pragma unroll
        for (int k = 0; k < 4; k++) d4[k] = __ldg(dp + k);

        #pragma unroll
        for (int k = 0; k < 4; k++) {
            float4 w;
            w.x = edge_weight(d4[k].x, cut, mean, sc, hpoc);
            w.y = edge_weight(d4[k].y, cut, mean, sc, hpoc);
            w.z = edge_weight(d4[k].z, cut, mean, sc, hpoc);
            w.w = edge_weight(d4[k].w, cut, mean, sc, hpoc);
            atomicAdd(op + k, w);        // RED.128
        }
    }
}

extern "C" void kernel_launch(void* const* d_in, const int* in_sizes, int n_in,
                              void* d_out, int out_size) {
    const float* feat = (const float*)d_in[0];   // (N,1)
    const float* dist = (const float*)d_in[1];   // (E,1)
    const float* rp   = (const float*)d_in[2];   // (16,3)
    const float* ftu  = (const float*)d_in[3];   // (8,)
    const int*   src  = (const int*)d_in[4];     // (E,)
    const int*   dst  = (const int*)d_in[5];     // (E,)
    float* out = (float*)d_out;

    int n_nodes = in_sizes[0]; (void)n_nodes;
    int n_edges = in_sizes[1];
    int epb = n_edges / 16;
    int n4 = out_size / 4;

    zero_counter_kernel<<<1, 1>>>();

    int workA = (n4 > n_edges) ? n4 : n_edges;
    prep_kernel<<<(workA + 255) / 256, 256>>>(
        (float4*)out, n4, feat, ftu, src, dst, n_edges);

    // Grid-stride; sized so the expected ~E/2 active edges fit in ~1 iteration.
    compute_kernel<<<1184, 256>>>(dist, rp, out, epb);
}

// round 5
// speedup vs baseline: 1.5567x; 1.5567x over previous
#include <cuda_runtime.h>

// AtomicConv edge aggregation, round 5: in-block smem compaction, 2 launches.
// K1: zero output + per-node type table (int8, L1-resident in K2).
// K2: per block: classify 512 edges -> smem worklist -> dense compute + RED.

#define MAX_NODES (1 << 20)
__device__ signed char g_type[MAX_NODES];

__global__ __launch_bounds__(256) void zero_and_type_kernel(
    float4* __restrict__ out, int n4,
    const float* __restrict__ feat, const float* __restrict__ ftu, int n_nodes)
{
    int i = blockIdx.x * 256 + threadIdx.x;
    if (i < n4) out[i] = make_float4(0.f, 0.f, 0.f, 0.f);
    if (i < n_nodes) {
        float f = __ldg(feat + i);
        signed char t = -1;
        #pragma unroll
        for (int j = 0; j < 8; j++)
            if (f == __ldg(ftu + j)) t = (signed char)j;
        g_type[i] = t;
    }
}

__device__ __forceinline__ float edge_weight(float d, float cut, float mean,
                                             float sc, float hpoc) {
    // 0.5*(cos(pi*d/cut)+1) == cos^2(pi*d/(2*cut))
    float c = __cosf(d * hpoc);
    float cv = c * c;
    cv = (d <= cut) ? cv : 0.f;
    float dm = d - mean;
    return cv * __expf(-sc * dm * dm);
}

constexpr int EDGES_PER_BLOCK = 512;   // 2 per thread

__global__ __launch_bounds__(256) void acnn_edge_kernel(
    const float* __restrict__ dist,   // (E) 16 contiguous dists per edge at r*16
    const float* __restrict__ rp,     // (16,3) [cutoff, mean, scaling]
    const int*   __restrict__ src,    // (E)
    const int*   __restrict__ dstv,   // (E)
    float*       __restrict__ out,    // (N,128)
    int n_edges, int epb)
{
    __shared__ uint2 s_list[EDGES_PER_BLOCK];   // {edge_id, dst*8+t}
    __shared__ float4 s_rp[16];                 // {cut, mean, sc, pi/(2*cut)}
    __shared__ unsigned s_cnt;

    int tid = threadIdx.x;
    int lane = tid & 31;

    if (tid == 0) s_cnt = 0u;
    if (tid < 16) {
        float cut  = __ldg(rp + 3 * tid + 0);
        float mean = __ldg(rp + 3 * tid + 1);
        float sc   = __ldg(rp + 3 * tid + 2);
        s_rp[tid] = make_float4(cut, mean, sc, 1.57079632679489662f / cut);
    }
    __syncthreads();

    int base = blockIdx.x * EDGES_PER_BLOCK;

    // ---- Phase 1: classify 2 edges/thread, warp-aggregated smem compaction ----
    int e0 = base + tid;
    int e1 = base + 256 + tid;
    bool v0 = (e0 < n_edges), v1 = (e1 < n_edges);

    int s0 = 0, s1 = 0;
    if (v0) s0 = __ldg(src + e0);
    if (v1) s1 = __ldg(src + e1);

    int t0 = -1, t1 = -1;
    if (v0) t0 = (int)g_type[s0];     // L1-resident 20KB table
    if (v1) t1 = (int)g_type[s1];
    bool a0 = v0 && (t0 >= 0);
    bool a1 = v1 && (t1 >= 0);

    int d0 = 0, d1 = 0;
    if (a0) d0 = __ldg(dstv + e0);
    if (a1) d1 = __ldg(dstv + e1);

    unsigned m0 = __ballot_sync(0xffffffffu, a0);
    unsigned m1 = __ballot_sync(0xffffffffu, a1);
    unsigned tot = (unsigned)(__popc(m0) + __popc(m1));
    unsigned wbase = 0;
    if (lane == 0 && tot) wbase = atomicAdd(&s_cnt, tot);
    wbase = __shfl_sync(0xffffffffu, wbase, 0);
    unsigned p0 = wbase + (unsigned)__popc(m0 & ((1u << lane) - 1u));
    unsigned p1 = wbase + (unsigned)__popc(m0)
                        + (unsigned)__popc(m1 & ((1u << lane) - 1u));
    if (a0) s_list[p0] = make_uint2((unsigned)e0, (unsigned)((d0 << 3) | t0));
    if (a1) s_list[p1] = make_uint2((unsigned)e1, (unsigned)((d1 << 3) | t1));

    __syncthreads();
    unsigned n_act = s_cnt;

    // ---- Phase 2: dense compute over compacted list ----
    for (unsigned i = tid; i < n_act; i += 256) {
        uint2 rec = s_list[i];
        int e = (int)rec.x;
        int q = e / epb;                 // radial kernel index
        int r = e - q * epb;

        float4 prm = s_rp[q];

        const float4* dp = reinterpret_cast<const float4*>(dist) + (r << 2);
        float4* op = reinterpret_cast<float4*>(out)
                   + (((int)(rec.y >> 3)) << 5) + (((int)(rec.y & 7u)) << 2);

        float4 d4[4];
        #pragma unroll
        for (int k = 0; k < 4; k++) d4[k] = __ldg(dp + k);

        #pragma unroll
        for (int k = 0; k < 4; k++) {
            float4 w;
            w.x = edge_weight(d4[k].x, prm.x, prm.y, prm.z, prm.w);
            w.y = edge_weight(d4[k].y, prm.x, prm.y, prm.z, prm.w);
            w.z = edge_weight(d4[k].z, prm.x, prm.y, prm.z, prm.w);
            w.w = edge_weight(d4[k].w, prm.x, prm.y, prm.z, prm.w);
            atomicAdd(op + k, w);        // RED.128
        }
    }
}

extern "C" void kernel_launch(void* const* d_in, const int* in_sizes, int n_in,
                              void* d_out, int out_size) {
    const float* feat = (const float*)d_in[0];   // (N,1)
    const float* dist = (const float*)d_in[1];   // (E,1)
    const float* rp   = (const float*)d_in[2];   // (16,3)
    const float* ftu  = (const float*)d_in[3];   // (8,)
    const int*   src  = (const int*)d_in[4];     // (E,)
    const int*   dst  = (const int*)d_in[5];     // (E,)
    float* out = (float*)d_out;

    int n_nodes = in_sizes[0];
    int n_edges = in_sizes[1];
    int epb = n_edges / 16;
    int n4 = out_size / 4;

    int workA = (n4 > n_nodes) ? n4 : n_nodes;
    zero_and_type_kernel<<<(workA + 255) / 256, 256>>>(
        (float4*)out, n4, feat, ftu, n_nodes);

    acnn_edge_kernel<<<(n_edges + EDGES_PER_BLOCK - 1) / EDGES_PER_BLOCK, 256>>>(
        dist, rp, src, dst, out, n_edges, epb);
}

// round 7
// speedup vs baseline: 1.7457x; 1.1214x over previous
#include <cuda_runtime.h>

// AtomicConv edge aggregation, round 6: barrier-free, EPT=2 @ full grid,
// L1-resident type table + precomputed float4 radial params.

#define MAX_NODES (1 << 20)
__device__ signed char g_type[MAX_NODES];
__device__ float4 g_rp4[16];   // {cut, mean, sc, pi/(2*cut)}

__global__ __launch_bounds__(256) void zero_and_type_kernel(
    float4* __restrict__ out, int n4,
    const float* __restrict__ feat, const float* __restrict__ ftu,
    const float* __restrict__ rp, int n_nodes)
{
    int i = blockIdx.x * 256 + threadIdx.x;
    if (i < n4) out[i] = make_float4(0.f, 0.f, 0.f, 0.f);
    if (i < n_nodes) {
        float f = __ldg(feat + i);
        signed char t = -1;
        #pragma unroll
        for (int j = 0; j < 8; j++)
            if (f == __ldg(ftu + j)) t = (signed char)j;
        g_type[i] = t;
    }
    if (blockIdx.x == 0 && threadIdx.x < 16) {
        float cut  = __ldg(rp + 3 * threadIdx.x + 0);
        float mean = __ldg(rp + 3 * threadIdx.x + 1);
        float sc   = __ldg(rp + 3 * threadIdx.x + 2);
        g_rp4[threadIdx.x] = make_float4(cut, mean, sc,
                                         1.57079632679489662f / cut);
    }
}

__device__ __forceinline__ float edge_weight(float d, float cut, float mean,
                                             float sc, float hpoc) {
    // 0.5*(cos(pi*d/cut)+1) == cos^2(pi*d/(2*cut))
    float c = __cosf(d * hpoc);
    float cv = c * c;
    cv = (d <= cut) ? cv : 0.f;
    float dm = d - mean;
    return cv * __expf(-sc * dm * dm);
}

__device__ __forceinline__ void process_edge(
    const float* __restrict__ dist, float* __restrict__ out,
    int e, int dn, int t, int epb, float inv_epb)
{
    // exact for e < 2^23 since rounding error << 0.5/epb
    int q = (int)(((float)e + 0.5f) * inv_epb);
    int r = e - q * epb;

    float4 prm = g_rp4[q];

    const float4* dp = reinterpret_cast<const float4*>(dist) + (r << 2);
    float4* op = reinterpret_cast<float4*>(out) + ((dn << 5) + (t << 2));

    float4 d4[4];
    #pragma unroll
    for (int k = 0; k < 4; k++) d4[k] = __ldg(dp + k);

    #pragma unroll
    for (int k = 0; k < 4; k++) {
        float4 w;
        w.x = edge_weight(d4[k].x, prm.x, prm.y, prm.z, prm.w);
        w.y = edge_weight(d4[k].y, prm.x, prm.y, prm.z, prm.w);
        w.z = edge_weight(d4[k].z, prm.x, prm.y, prm.z, prm.w);
        w.w = edge_weight(d4[k].w, prm.x, prm.y, prm.z, prm.w);
        atomicAdd(op + k, w);          // RED.128
    }
}

__global__ __launch_bounds__(256) void acnn_edge_kernel(
    const float* __restrict__ dist,   // (E) 16 contiguous dists per edge at r*16
    const int*   __restrict__ src,    // (E)
    const int*   __restrict__ dstv,   // (E)
    float*       __restrict__ out,    // (N,128)
    int n_edges, int epb, float inv_epb)
{
    int tid = threadIdx.x;
    int e0 = blockIdx.x * 512 + tid;
    int e1 = e0 + 256;
    bool v0 = (e0 < n_edges), v1 = (e1 < n_edges);

    // Phase-batched front loads: 4 coalesced LDGs in flight
    int s0 = 0, s1 = 0, d0 = 0, d1 = 0;
    if (v0) s0 = __ldg(src + e0);
    if (v1) s1 = __ldg(src + e1);
    if (v0) d0 = __ldg(dstv + e0);
    if (v1) d1 = __ldg(dstv + e1);

    // Both random type gathers in flight (L1-resident 20KB table)
    int t0 = v0 ? (int)g_type[s0] : -1;
    int t1 = v1 ? (int)g_type[s1] : -1;

    if (t0 >= 0) process_edge(dist, out, e0, d0, t0, epb, inv_epb);
    if (t1 >= 0) process_edge(dist, out, e1, d1, t1, epb, inv_epb);
}

extern "C" void kernel_launch(void* const* d_in, const int* in_sizes, int n_in,
                              void* d_out, int out_size) {
    const float* feat = (const float*)d_in[0];   // (N,1)
    const float* dist = (const float*)d_in[1];   // (E,1)
    const float* rp   = (const float*)d_in[2];   // (16,3)
    const float* ftu  = (const float*)d_in[3];   // (8,)
    const int*   src  = (const int*)d_in[4];     // (E,)
    const int*   dst  = (const int*)d_in[5];     // (E,)
    float* out = (float*)d_out;

    int n_nodes = in_sizes[0];
    int n_edges = in_sizes[1];
    int epb = n_edges / 16;
    float inv_epb = 1.0f / (float)epb;
    int n4 = out_size / 4;

    int workA = (n4 > n_nodes) ? n4 : n_nodes;
    zero_and_type_kernel<<<(workA + 255) / 256, 256>>>(
        (float4*)out, n4, feat, ftu, rp, n_nodes);

    acnn_edge_kernel<<<(n_edges + 511) / 512, 256>>>(
        dist, src, dst, out, n_edges, epb, inv_epb);
}